// round 9
// baseline (speedup 1.0000x reference)
#include <cuda_runtime.h>
#include <cuda_fp16.h>

#define N_NODES 50000
#define N_EDGES 1600000
#define FDIM    128
#define GN      8
#define CAP     128          // per-node edge bucket capacity (max degree ~58)

#define GEMM_BLOCKS   ((N_NODES + 63) / 64)          // 782
#define SCAT_BLOCKS   ((N_EDGES / 2 + 255) / 256)    // 3125
#define FUSED_BLOCKS  (GEMM_BLOCKS + SCAT_BLOCKS)    // 3907 (= 782*5 - 3, mix 1:4)
#define PACK_BLOCKS   196
#define WDWS_BLOCKS   32

// Scratch (static __device__ arrays: allocation-free per harness rules)
static __device__ __half2 g_hh[(size_t)N_NODES * (FDIM / 2)];   // 12.8 MB
static __device__ float g_sd[N_NODES];
static __device__ float g_ss[N_NODES];
static __device__ float g_Wp[FDIM * FDIM];
static __device__ float g_wd[FDIM];      // W @ a_dst
static __device__ float g_ws[FDIM];      // W @ a_src
static __device__ int   g_cnt[N_NODES];
static __device__ int2  g_csr[(size_t)N_NODES * CAP];           // (src, score-bits)

#define FMA_F32X2(d, a, b, c) \
    asm("fma.rn.f32x2 %0, %1, %2, %3;" : "=l"(d) : "l"(a), "l"(b), "l"(c))

__device__ __forceinline__ unsigned long long pack_f2(float2 v) {
    return *reinterpret_cast<unsigned long long*>(&v);
}

// ---------------------------------------------------------------------------
// Setup: pack W (k-pair-interleave), zero counters, wd/ws = W @ a_{dst,src}.
// ---------------------------------------------------------------------------
__global__ __launch_bounds__(256) void setup_kernel(
    const float* __restrict__ W, const float* __restrict__ attn)
{
    if (blockIdx.x < PACK_BLOCKS) {
        int i = blockIdx.x * 256 + threadIdx.x;
        if (i < FDIM * FDIM) {
            int kp = i >> 8;
            int j  = i & 255;
            g_Wp[i] = W[(2 * kp + (j & 1)) * FDIM + (j >> 1)];
        }
        if (i < N_NODES) g_cnt[i] = 0;
    } else {
        int warp = threadIdx.x >> 5;
        int lane = threadIdx.x & 31;
        int o = (blockIdx.x - PACK_BLOCKS) * 8 + warp;
        int k = o & 127;
        int which = o >> 7;
        float4 wv = reinterpret_cast<const float4*>(W + k * FDIM)[lane];
        float4 av = reinterpret_cast<const float4*>(attn + which * FDIM)[lane];
        float d = wv.x * av.x + wv.y * av.y + wv.z * av.z + wv.w * av.w;
        #pragma unroll
        for (int off = 16; off; off >>= 1)
            d += __shfl_xor_sync(0xffffffffu, d, off);
        if (lane == 0) {
            if (which == 0) g_wd[k] = d; else g_ws[k] = d;
        }
    }
}

// ---------------------------------------------------------------------------
// Per-node scores: sd[n] = X[n]·wd, ss[n] = X[n]·ws. One warp per node.
// ---------------------------------------------------------------------------
__global__ __launch_bounds__(256) void score_kernel(const float* __restrict__ X)
{
    int n    = (blockIdx.x * blockDim.x + threadIdx.x) >> 5;
    int lane = threadIdx.x & 31;
    if (n >= N_NODES) return;
    float4 xv = reinterpret_cast<const float4*>(X + (size_t)n * FDIM)[lane];
    float4 wd = reinterpret_cast<const float4*>(g_wd)[lane];
    float4 ws = reinterpret_cast<const float4*>(g_ws)[lane];
    float pd = xv.x * wd.x + xv.y * wd.y + xv.z * wd.z + xv.w * wd.w;
    float ps = xv.x * ws.x + xv.y * ws.y + xv.z * ws.z + xv.w * ws.w;
    #pragma unroll
    for (int off = 16; off; off >>= 1) {
        pd += __shfl_xor_sync(0xffffffffu, pd, off);
        ps += __shfl_xor_sync(0xffffffffu, ps, off);
    }
    if (lane == 0) { g_sd[n] = pd; g_ss[n] = ps; }
}

// ---------------------------------------------------------------------------
// FUSED, INTERLEAVED: bid % 5 == 0 -> GEMM tile (782 of 3907); else scatter
// (3125). Every scheduling wave carries the 1:4 mix so FFMA-heavy GEMM warps
// and memory/atomic-heavy scatter warps co-reside on each SM.
// ---------------------------------------------------------------------------
__global__ __launch_bounds__(256) void fused_kernel(
    const float* __restrict__ X, const int4* __restrict__ E4)
{
    int r = blockIdx.x % 5;
    int q = blockIdx.x / 5;
    if (r == 0) {
        // ---------------- GEMM branch (tile q of 782) ----------------
        const int warp = threadIdx.x >> 5;
        const int lane = threadIdx.x & 31;
        const int node0 = (q * 8 + warp) * GN;

        __shared__ __align__(16) float xs[8][GN][FDIM];   // 32 KB

        #pragma unroll
        for (int n = 0; n < GN; n++) {
            int node = node0 + n;
            float4 v = make_float4(0.f, 0.f, 0.f, 0.f);
            if (node < N_NODES)
                v = reinterpret_cast<const float4*>(X + (size_t)node * FDIM)[lane];
            reinterpret_cast<float4*>(xs[warp][n])[lane] = v;
        }
        __syncwarp();

        unsigned long long acc[GN][4];
        #pragma unroll
        for (int n = 0; n < GN; n++)
            acc[n][0] = acc[n][1] = acc[n][2] = acc[n][3] = 0ull;

        const ulonglong2* wp = reinterpret_cast<const ulonglong2*>(g_Wp) + lane * 2;

        #pragma unroll 2
        for (int kp = 0; kp < FDIM / 2; kp++) {
            ulonglong2 wa = wp[kp * 64 + 0];
            ulonglong2 wb = wp[kp * 64 + 1];
            #pragma unroll
            for (int n = 0; n < GN; n++) {
                unsigned long long xx =
                    *reinterpret_cast<const unsigned long long*>(&xs[warp][n][kp * 2]);
                FMA_F32X2(acc[n][0], xx, wa.x, acc[n][0]);
                FMA_F32X2(acc[n][1], xx, wa.y, acc[n][1]);
                FMA_F32X2(acc[n][2], xx, wb.x, acc[n][2]);
                FMA_F32X2(acc[n][3], xx, wb.y, acc[n][3]);
            }
        }

        #pragma unroll
        for (int n = 0; n < GN; n++) {
            int node = node0 + n;
            if (node < N_NODES) {
                float rr[4];
                #pragma unroll
                for (int c = 0; c < 4; c++) {
                    float2 u = *reinterpret_cast<float2*>(&acc[n][c]);
                    rr[c] = u.x + u.y;
                }
                __half2 p0 = __floats2half2_rn(rr[0], rr[1]);
                __half2 p1 = __floats2half2_rn(rr[2], rr[3]);
                uint2 packed;
                packed.x = *reinterpret_cast<unsigned int*>(&p0);
                packed.y = *reinterpret_cast<unsigned int*>(&p1);
                reinterpret_cast<uint2*>(g_hh)[(size_t)node * 32 + lane] = packed;
            }
        }
    } else {
        // ---------------- scatter branch (index q*4 + r-1 of 3125) ----------
        int sb = q * 4 + (r - 1);
        int i = sb * 256 + threadIdx.x;
        if (i >= N_EDGES / 2) return;
        int4 e = E4[i];             // (dst0, src0, dst1, src1)

        float sc0 = g_sd[e.x] + g_ss[e.y];
        sc0 = sc0 > 0.f ? sc0 : 0.2f * sc0;
        sc0 = fminf(2.f, fmaxf(-2.f, sc0));
        float s0 = __expf(sc0);

        float sc1 = g_sd[e.z] + g_ss[e.w];
        sc1 = sc1 > 0.f ? sc1 : 0.2f * sc1;
        sc1 = fminf(2.f, fmaxf(-2.f, sc1));
        float s1 = __expf(sc1);

        int p0 = atomicAdd(&g_cnt[e.x], 1);
        g_csr[(size_t)e.x * CAP + p0] = make_int2(e.y, __float_as_int(s0));
        int p1 = atomicAdd(&g_cnt[e.z], 1);
        g_csr[(size_t)e.z * CAP + p1] = make_int2(e.w, __float_as_int(s1));
    }
}

// ---------------------------------------------------------------------------
// One warp per dst node: 8 edges/iter, all 8 gathers + metadata front-batched
// (MLP ~8), packed f32x2 FFMA accumulation, normalize, STG.128.
// ---------------------------------------------------------------------------
__global__ __launch_bounds__(256) void agg_kernel(float* __restrict__ out) {
    int w    = (blockIdx.x * blockDim.x + threadIdx.x) >> 5;
    int lane = threadIdx.x & 31;
    if (w >= N_NODES) return;

    int cnt = g_cnt[w];
    const int2* row = g_csr + (size_t)w * CAP;
    const uint2* hh = reinterpret_cast<const uint2*>(g_hh);

    unsigned long long accA = 0ull, accB = 0ull;   // packed (c0,c1), (c2,c3)
    float ssum = 0.f;

    #define ACCUM(V, WT) { \
        float2 f0 = __half22float2(*reinterpret_cast<__half2*>(&(V).x)); \
        float2 f1 = __half22float2(*reinterpret_cast<__half2*>(&(V).y)); \
        unsigned long long ww = pack_f2(make_float2((WT), (WT))); \
        FMA_F32X2(accA, ww, pack_f2(f0), accA); \
        FMA_F32X2(accB, ww, pack_f2(f1), accB); }

    int e = 0;
    for (; e + 8 <= cnt; e += 8) {
        int4 m[4];
        m[0] = *reinterpret_cast<const int4*>(row + e);
        m[1] = *reinterpret_cast<const int4*>(row + e + 2);
        m[2] = *reinterpret_cast<const int4*>(row + e + 4);
        m[3] = *reinterpret_cast<const int4*>(row + e + 6);
        uint2 v[8];
        #pragma unroll
        for (int u = 0; u < 4; u++) {
            v[2*u]     = hh[(unsigned int)m[u].x * 32u + lane];
            v[2*u + 1] = hh[(unsigned int)m[u].z * 32u + lane];
        }
        #pragma unroll
        for (int u = 0; u < 4; u++) {
            float w0 = __int_as_float(m[u].y), w1 = __int_as_float(m[u].w);
            ACCUM(v[2*u], w0) ACCUM(v[2*u + 1], w1)
            ssum += w0 + w1;
        }
    }
    for (; e + 2 <= cnt; e += 2) {
        int4 m01 = *reinterpret_cast<const int4*>(row + e);
        float w0 = __int_as_float(m01.y), w1 = __int_as_float(m01.w);
        uint2 v0 = hh[(unsigned int)m01.x * 32u + lane];
        uint2 v1 = hh[(unsigned int)m01.z * 32u + lane];
        ACCUM(v0, w0) ACCUM(v1, w1)
        ssum += w0 + w1;
    }
    if (e < cnt) {
        int2 ee = row[e];
        float w0 = __int_as_float(ee.y);
        uint2 v0 = hh[(unsigned int)ee.x * 32u + lane];
        ACCUM(v0, w0)
        ssum += w0;
    }
    #undef ACCUM

    float2 rA = *reinterpret_cast<float2*>(&accA);
    float2 rB = *reinterpret_cast<float2*>(&accB);
    float inv = (ssum > 0.f) ? (1.f / ssum) : 0.f;
    reinterpret_cast<float4*>(out)[(size_t)w * 32 + lane] =
        make_float4(rA.x * inv, rA.y * inv, rB.x * inv, rB.y * inv);
}

// ---------------------------------------------------------------------------
extern "C" void kernel_launch(void* const* d_in, const int* in_sizes, int n_in,
                              void* d_out, int out_size)
{
    const float* X    = (const float*)d_in[0];   // node_states (50000,128)
    const int4*  E4   = (const int4*) d_in[1];   // edges as 2-edge packs
    const float* W    = (const float*)d_in[2];   // kernel (128,128)
    const float* attn = (const float*)d_in[3];   // kernel_attention (256,1)
    float* out = (float*)d_out;

    setup_kernel<<<PACK_BLOCKS + WDWS_BLOCKS, 256>>>(W, attn);
    score_kernel<<<(N_NODES * 32 + 255) / 256, 256>>>(X);
    fused_kernel<<<FUSED_BLOCKS, 256>>>(X, E4);
    agg_kernel<<<(N_NODES * 32 + 255) / 256, 256>>>(out);
}

// round 10
// speedup vs baseline: 1.0962x; 1.0962x over previous
#include <cuda_runtime.h>
#include <cuda_fp16.h>

#define N_NODES 50000
#define N_EDGES 1600000
#define FDIM    128
#define GN      8
#define CAP     128          // per-node edge bucket capacity (max degree ~58)

#define GEMM_BLOCKS   ((N_NODES + 63) / 64)          // 782
#define SCAT_BLOCKS   ((N_EDGES / 4 + 255) / 256)    // 1563 (4 edges/thread)
#define PACK_BLOCKS   196
#define WDWS_BLOCKS   32

// Scratch (static __device__ arrays: allocation-free per harness rules)
static __device__ __half2 g_hh[(size_t)N_NODES * (FDIM / 2)];   // 12.8 MB
static __device__ float g_sd[N_NODES];
static __device__ float g_ss[N_NODES];
static __device__ float g_Wp[FDIM * FDIM];
static __device__ float g_wd[FDIM];      // W @ a_dst
static __device__ float g_ws[FDIM];      // W @ a_src
static __device__ int   g_cnt[N_NODES];
static __device__ int2  g_csr[(size_t)N_NODES * CAP];           // (src, score-bits)

#define FMA_F32X2(d, a, b, c) \
    asm("fma.rn.f32x2 %0, %1, %2, %3;" : "=l"(d) : "l"(a), "l"(b), "l"(c))

__device__ __forceinline__ unsigned long long pack_f2(float2 v) {
    return *reinterpret_cast<unsigned long long*>(&v);
}

// ---------------------------------------------------------------------------
// Setup: pack W (k-pair-interleave), zero counters, wd/ws = W @ a_{dst,src}.
// ---------------------------------------------------------------------------
__global__ __launch_bounds__(256) void setup_kernel(
    const float* __restrict__ W, const float* __restrict__ attn)
{
    if (blockIdx.x < PACK_BLOCKS) {
        int i = blockIdx.x * 256 + threadIdx.x;
        if (i < FDIM * FDIM) {
            int kp = i >> 8;
            int j  = i & 255;
            g_Wp[i] = W[(2 * kp + (j & 1)) * FDIM + (j >> 1)];
        }
        if (i < N_NODES) g_cnt[i] = 0;
    } else {
        int warp = threadIdx.x >> 5;
        int lane = threadIdx.x & 31;
        int o = (blockIdx.x - PACK_BLOCKS) * 8 + warp;
        int k = o & 127;
        int which = o >> 7;
        float4 wv = reinterpret_cast<const float4*>(W + k * FDIM)[lane];
        float4 av = reinterpret_cast<const float4*>(attn + which * FDIM)[lane];
        float d = wv.x * av.x + wv.y * av.y + wv.z * av.z + wv.w * av.w;
        #pragma unroll
        for (int off = 16; off; off >>= 1)
            d += __shfl_xor_sync(0xffffffffu, d, off);
        if (lane == 0) {
            if (which == 0) g_wd[k] = d; else g_ws[k] = d;
        }
    }
}

// ---------------------------------------------------------------------------
// Per-node scores: sd[n] = X[n]·wd, ss[n] = X[n]·ws. One warp per node.
// ---------------------------------------------------------------------------
__global__ __launch_bounds__(256) void score_kernel(const float* __restrict__ X)
{
    int n    = (blockIdx.x * blockDim.x + threadIdx.x) >> 5;
    int lane = threadIdx.x & 31;
    if (n >= N_NODES) return;
    float4 xv = reinterpret_cast<const float4*>(X + (size_t)n * FDIM)[lane];
    float4 wd = reinterpret_cast<const float4*>(g_wd)[lane];
    float4 ws = reinterpret_cast<const float4*>(g_ws)[lane];
    float pd = xv.x * wd.x + xv.y * wd.y + xv.z * wd.z + xv.w * wd.w;
    float ps = xv.x * ws.x + xv.y * ws.y + xv.z * ws.z + xv.w * ws.w;
    #pragma unroll
    for (int off = 16; off; off >>= 1) {
        pd += __shfl_xor_sync(0xffffffffu, pd, off);
        ps += __shfl_xor_sync(0xffffffffu, ps, off);
    }
    if (lane == 0) { g_sd[n] = pd; g_ss[n] = ps; }
}

// ---------------------------------------------------------------------------
// FUSED (round-8 sequential layout): blocks [0, GEMM_BLOCKS) = GEMM;
// rest = scatter at 4 edges/thread (MLP 4 on the atomic->store chains).
// ---------------------------------------------------------------------------
__global__ __launch_bounds__(256) void fused_kernel(
    const float* __restrict__ X, const int4* __restrict__ E4)
{
    if (blockIdx.x < GEMM_BLOCKS) {
        // ---------------- GEMM branch ----------------
        const int warp = threadIdx.x >> 5;
        const int lane = threadIdx.x & 31;
        const int node0 = (blockIdx.x * 8 + warp) * GN;

        __shared__ __align__(16) float xs[8][GN][FDIM];   // 32 KB

        #pragma unroll
        for (int n = 0; n < GN; n++) {
            int node = node0 + n;
            float4 v = make_float4(0.f, 0.f, 0.f, 0.f);
            if (node < N_NODES)
                v = reinterpret_cast<const float4*>(X + (size_t)node * FDIM)[lane];
            reinterpret_cast<float4*>(xs[warp][n])[lane] = v;
        }
        __syncwarp();

        unsigned long long acc[GN][4];
        #pragma unroll
        for (int n = 0; n < GN; n++)
            acc[n][0] = acc[n][1] = acc[n][2] = acc[n][3] = 0ull;

        const ulonglong2* wp = reinterpret_cast<const ulonglong2*>(g_Wp) + lane * 2;

        #pragma unroll 2
        for (int kp = 0; kp < FDIM / 2; kp++) {
            ulonglong2 wa = wp[kp * 64 + 0];
            ulonglong2 wb = wp[kp * 64 + 1];
            #pragma unroll
            for (int n = 0; n < GN; n++) {
                unsigned long long xx =
                    *reinterpret_cast<const unsigned long long*>(&xs[warp][n][kp * 2]);
                FMA_F32X2(acc[n][0], xx, wa.x, acc[n][0]);
                FMA_F32X2(acc[n][1], xx, wa.y, acc[n][1]);
                FMA_F32X2(acc[n][2], xx, wb.x, acc[n][2]);
                FMA_F32X2(acc[n][3], xx, wb.y, acc[n][3]);
            }
        }

        #pragma unroll
        for (int n = 0; n < GN; n++) {
            int node = node0 + n;
            if (node < N_NODES) {
                float rr[4];
                #pragma unroll
                for (int c = 0; c < 4; c++) {
                    float2 u = *reinterpret_cast<float2*>(&acc[n][c]);
                    rr[c] = u.x + u.y;
                }
                __half2 p0 = __floats2half2_rn(rr[0], rr[1]);
                __half2 p1 = __floats2half2_rn(rr[2], rr[3]);
                uint2 packed;
                packed.x = *reinterpret_cast<unsigned int*>(&p0);
                packed.y = *reinterpret_cast<unsigned int*>(&p1);
                reinterpret_cast<uint2*>(g_hh)[(size_t)node * 32 + lane] = packed;
            }
        }
    } else {
        // ---------------- scatter branch: 4 edges/thread ----------------
        int i = (blockIdx.x - GEMM_BLOCKS) * 256 + threadIdx.x;   // pair-of-pairs id
        if (i >= N_EDGES / 4) return;
        int4 ea = E4[i * 2];          // (dst0, src0, dst1, src1)
        int4 eb = E4[i * 2 + 1];      // (dst2, src2, dst3, src3)

        #define SCORE(D, S, OUTV) { \
            float sc = g_sd[D] + g_ss[S]; \
            sc = sc > 0.f ? sc : 0.2f * sc; \
            sc = fminf(2.f, fmaxf(-2.f, sc)); \
            OUTV = __expf(sc); }

        float s0, s1, s2, s3;
        SCORE(ea.x, ea.y, s0)
        SCORE(ea.z, ea.w, s1)
        SCORE(eb.x, eb.y, s2)
        SCORE(eb.z, eb.w, s3)
        #undef SCORE

        int p0 = atomicAdd(&g_cnt[ea.x], 1);
        int p1 = atomicAdd(&g_cnt[ea.z], 1);
        int p2 = atomicAdd(&g_cnt[eb.x], 1);
        int p3 = atomicAdd(&g_cnt[eb.z], 1);
        g_csr[(unsigned int)ea.x * CAP + p0] = make_int2(ea.y, __float_as_int(s0));
        g_csr[(unsigned int)ea.z * CAP + p1] = make_int2(ea.w, __float_as_int(s1));
        g_csr[(unsigned int)eb.x * CAP + p2] = make_int2(eb.y, __float_as_int(s2));
        g_csr[(unsigned int)eb.z * CAP + p3] = make_int2(eb.w, __float_as_int(s3));
    }
}

// ---------------------------------------------------------------------------
// One warp per dst node (round-8 measured-good form, 32-bit indexing):
// 4 edges/iter, int4 metadata loads, packed f32x2 FFMA accumulation.
// ---------------------------------------------------------------------------
__global__ __launch_bounds__(256) void agg_kernel(float* __restrict__ out) {
    int w    = (blockIdx.x * blockDim.x + threadIdx.x) >> 5;
    int lane = threadIdx.x & 31;
    if (w >= N_NODES) return;

    int cnt = g_cnt[w];
    const int2* row = g_csr + (unsigned int)w * CAP;
    const uint2* hh = reinterpret_cast<const uint2*>(g_hh);

    unsigned long long accA = 0ull, accB = 0ull;   // packed (c0,c1), (c2,c3)
    float ssum = 0.f;

    #define ACCUM(V, WT) { \
        float2 f0 = __half22float2(*reinterpret_cast<__half2*>(&(V).x)); \
        float2 f1 = __half22float2(*reinterpret_cast<__half2*>(&(V).y)); \
        unsigned long long ww = pack_f2(make_float2((WT), (WT))); \
        FMA_F32X2(accA, ww, pack_f2(f0), accA); \
        FMA_F32X2(accB, ww, pack_f2(f1), accB); }

    int e = 0;
    for (; e + 4 <= cnt; e += 4) {
        int4 m01 = *reinterpret_cast<const int4*>(row + e);
        int4 m23 = *reinterpret_cast<const int4*>(row + e + 2);
        float w0 = __int_as_float(m01.y), w1 = __int_as_float(m01.w);
        float w2 = __int_as_float(m23.y), w3 = __int_as_float(m23.w);
        uint2 v0 = hh[(unsigned int)m01.x * 32u + lane];
        uint2 v1 = hh[(unsigned int)m01.z * 32u + lane];
        uint2 v2 = hh[(unsigned int)m23.x * 32u + lane];
        uint2 v3 = hh[(unsigned int)m23.z * 32u + lane];
        ACCUM(v0, w0) ACCUM(v1, w1) ACCUM(v2, w2) ACCUM(v3, w3)
        ssum += (w0 + w1) + (w2 + w3);
    }
    for (; e < cnt; e++) {
        int2 ee = row[e];
        float w0 = __int_as_float(ee.y);
        uint2 v0 = hh[(unsigned int)ee.x * 32u + lane];
        ACCUM(v0, w0)
        ssum += w0;
    }
    #undef ACCUM

    float2 rA = *reinterpret_cast<float2*>(&accA);
    float2 rB = *reinterpret_cast<float2*>(&accB);
    float inv = (ssum > 0.f) ? (1.f / ssum) : 0.f;
    reinterpret_cast<float4*>(out)[(unsigned int)w * 32u + lane] =
        make_float4(rA.x * inv, rA.y * inv, rB.x * inv, rB.y * inv);
}

// ---------------------------------------------------------------------------
extern "C" void kernel_launch(void* const* d_in, const int* in_sizes, int n_in,
                              void* d_out, int out_size)
{
    const float* X    = (const float*)d_in[0];   // node_states (50000,128)
    const int4*  E4   = (const int4*) d_in[1];   // edges as 2-edge packs
    const float* W    = (const float*)d_in[2];   // kernel (128,128)
    const float* attn = (const float*)d_in[3];   // kernel_attention (256,1)
    float* out = (float*)d_out;

    setup_kernel<<<PACK_BLOCKS + WDWS_BLOCKS, 256>>>(W, attn);
    score_kernel<<<(N_NODES * 32 + 255) / 256, 256>>>(X);
    fused_kernel<<<GEMM_BLOCKS + SCAT_BLOCKS, 256>>>(X, E4);
    agg_kernel<<<(N_NODES * 32 + 255) / 256, 256>>>(out);
}

// round 11
// speedup vs baseline: 1.3274x; 1.2109x over previous
#include <cuda_runtime.h>
#include <cuda_fp16.h>
#include <cstdint>

#define N_NODES 50000
#define N_EDGES 1600000
#define FDIM    128
#define CAP     128          // per-node edge bucket capacity (max degree ~58)

#define GEMM_BLOCKS ((N_NODES + 127) / 128)          // 391
#define SCAT_BLOCKS ((N_EDGES / 4 + 255) / 256)      // 1563
#define WPAD        136                               // Wt row pad (halfs) -> conflict-free

// Scratch (static __device__ arrays: allocation-free per harness rules)
static __device__ __half2 g_hh[(size_t)N_NODES * (FDIM / 2)];   // 12.8 MB
static __device__ float g_sd[N_NODES];
static __device__ float g_ss[N_NODES];
static __device__ int   g_cnt[N_NODES];
static __device__ int2  g_csr[(size_t)N_NODES * CAP];           // (src, score-bits)

#define FMA_F32X2(d, a, b, c) \
    asm("fma.rn.f32x2 %0, %1, %2, %3;" : "=l"(d) : "l"(a), "l"(b), "l"(c))

__device__ __forceinline__ unsigned long long pack_f2(float2 v) {
    return *reinterpret_cast<unsigned long long*>(&v);
}
__device__ __forceinline__ uint32_t f2_to_h2(float2 v) {
    __half2 h = __floats2half2_rn(v.x, v.y);
    return *reinterpret_cast<uint32_t*>(&h);
}

// ---------------------------------------------------------------------------
// GEMM + scores via HMMA (mma.sync m16n8k16 f16->f32):
//  - zero slice of g_cnt (50048 ids across 391 blocks)
//  - stage W transposed to fp16 smem Wt[n][k] (pad 136 -> conflict-free LDS)
//  - warp computes 16 rows x 128 cols; A-frags straight from global X
//  - epilogue: fp16 h store + score dots (h·a_dst, h·a_src) with 4-lane reduce
// ---------------------------------------------------------------------------
__global__ __launch_bounds__(256) void gemm_score_mma(
    const float* __restrict__ X, const float* __restrict__ W,
    const float* __restrict__ attn)
{
    // fold counter zeroing into this kernel (scatter runs in a later launch)
    int zi = blockIdx.x * 128 + threadIdx.x;
    if (threadIdx.x < 128 && zi < N_NODES) g_cnt[zi] = 0;

    __shared__ __align__(16) __half wt[FDIM * WPAD];   // 34.8 KB

    for (int idx = threadIdx.x; idx < FDIM * FDIM; idx += 256) {
        int k = idx >> 7, n = idx & 127;
        wt[n * WPAD + k] = __float2half_rn(W[idx]);    // W[k][n] -> Wt[n][k]
    }
    __syncthreads();

    const int warp = threadIdx.x >> 5;
    const int lane = threadIdx.x & 31;
    const int g = lane >> 2;       // group id (0..7)
    const int t = lane & 3;        // thread-in-group

    const int m0   = blockIdx.x * 128 + warp * 16;
    const int row0 = m0 + g;
    const int row1 = m0 + g + 8;
    const int lr0  = min(row0, N_NODES - 1);
    const int lr1  = min(row1, N_NODES - 1);

    const float* x0 = X + (size_t)lr0 * FDIM;
    const float* x1 = X + (size_t)lr1 * FDIM;
    const uint32_t* wtw = reinterpret_cast<const uint32_t*>(wt);   // 68 words/row

    float acc[16][4];
    #pragma unroll
    for (int nt = 0; nt < 16; nt++)
        acc[nt][0] = acc[nt][1] = acc[nt][2] = acc[nt][3] = 0.f;

    #pragma unroll
    for (int kc = 0; kc < 8; kc++) {
        int k0 = kc * 16 + 2 * t;
        uint32_t a0 = f2_to_h2(*reinterpret_cast<const float2*>(x0 + k0));
        uint32_t a1 = f2_to_h2(*reinterpret_cast<const float2*>(x1 + k0));
        uint32_t a2 = f2_to_h2(*reinterpret_cast<const float2*>(x0 + k0 + 8));
        uint32_t a3 = f2_to_h2(*reinterpret_cast<const float2*>(x1 + k0 + 8));
        #pragma unroll
        for (int nt = 0; nt < 16; nt++) {
            int bw = (nt * 8 + g) * (WPAD / 2) + kc * 8 + t;
            uint32_t b0 = wtw[bw];
            uint32_t b1 = wtw[bw + 4];
            asm volatile(
                "mma.sync.aligned.m16n8k16.row.col.f32.f16.f16.f32 "
                "{%0,%1,%2,%3}, {%4,%5,%6,%7}, {%8,%9}, {%0,%1,%2,%3};"
                : "+f"(acc[nt][0]), "+f"(acc[nt][1]),
                  "+f"(acc[nt][2]), "+f"(acc[nt][3])
                : "r"(a0), "r"(a1), "r"(a2), "r"(a3), "r"(b0), "r"(b1));
        }
    }

    // Epilogue: h fp16 store + score partial dots
    float pd0 = 0.f, ps0 = 0.f, pd1 = 0.f, ps1 = 0.f;
    #pragma unroll
    for (int nt = 0; nt < 16; nt++) {
        int c0 = nt * 8 + 2 * t;                 // even -> 8B-aligned float2
        float2 ad = *reinterpret_cast<const float2*>(attn + c0);
        float2 as = *reinterpret_cast<const float2*>(attn + FDIM + c0);
        pd0 += acc[nt][0] * ad.x + acc[nt][1] * ad.y;
        ps0 += acc[nt][0] * as.x + acc[nt][1] * as.y;
        pd1 += acc[nt][2] * ad.x + acc[nt][3] * ad.y;
        ps1 += acc[nt][2] * as.x + acc[nt][3] * as.y;
        if (row0 < N_NODES)
            g_hh[(unsigned int)row0 * 64u + nt * 4 + t] =
                __floats2half2_rn(acc[nt][0], acc[nt][1]);
        if (row1 < N_NODES)
            g_hh[(unsigned int)row1 * 64u + nt * 4 + t] =
                __floats2half2_rn(acc[nt][2], acc[nt][3]);
    }
    // reduce across the 4 lanes of each group (t dimension)
    #pragma unroll
    for (int off = 1; off < 4; off <<= 1) {
        pd0 += __shfl_xor_sync(0xffffffffu, pd0, off);
        ps0 += __shfl_xor_sync(0xffffffffu, ps0, off);
        pd1 += __shfl_xor_sync(0xffffffffu, pd1, off);
        ps1 += __shfl_xor_sync(0xffffffffu, ps1, off);
    }
    if (t == 0) {
        if (row0 < N_NODES) { g_sd[row0] = pd0; g_ss[row0] = ps0; }
        if (row1 < N_NODES) { g_sd[row1] = pd1; g_ss[row1] = ps1; }
    }
}

// ---------------------------------------------------------------------------
// Scatter (round-10 measured-good form): 4 edges/thread, direct buckets.
// ---------------------------------------------------------------------------
__global__ __launch_bounds__(256) void scatter_kernel(const int4* __restrict__ E4) {
    int i = blockIdx.x * 256 + threadIdx.x;     // pair-of-pairs id
    if (i >= N_EDGES / 4) return;
    int4 ea = E4[i * 2];          // (dst0, src0, dst1, src1)
    int4 eb = E4[i * 2 + 1];      // (dst2, src2, dst3, src3)

    #define SCORE(D, S, OUTV) { \
        float sc = g_sd[D] + g_ss[S]; \
        sc = sc > 0.f ? sc : 0.2f * sc; \
        sc = fminf(2.f, fmaxf(-2.f, sc)); \
        OUTV = __expf(sc); }

    float s0, s1, s2, s3;
    SCORE(ea.x, ea.y, s0)
    SCORE(ea.z, ea.w, s1)
    SCORE(eb.x, eb.y, s2)
    SCORE(eb.z, eb.w, s3)
    #undef SCORE

    int p0 = atomicAdd(&g_cnt[ea.x], 1);
    int p1 = atomicAdd(&g_cnt[ea.z], 1);
    int p2 = atomicAdd(&g_cnt[eb.x], 1);
    int p3 = atomicAdd(&g_cnt[eb.z], 1);
    g_csr[(unsigned int)ea.x * CAP + p0] = make_int2(ea.y, __float_as_int(s0));
    g_csr[(unsigned int)ea.z * CAP + p1] = make_int2(ea.w, __float_as_int(s1));
    g_csr[(unsigned int)eb.x * CAP + p2] = make_int2(eb.y, __float_as_int(s2));
    g_csr[(unsigned int)eb.z * CAP + p3] = make_int2(eb.w, __float_as_int(s3));
}

// ---------------------------------------------------------------------------
// Agg (round-10 measured-good form): warp/node, 4 edges/iter, FFMA2 accum.
// ---------------------------------------------------------------------------
__global__ __launch_bounds__(256) void agg_kernel(float* __restrict__ out) {
    int w    = (blockIdx.x * blockDim.x + threadIdx.x) >> 5;
    int lane = threadIdx.x & 31;
    if (w >= N_NODES) return;

    int cnt = g_cnt[w];
    const int2* row = g_csr + (unsigned int)w * CAP;
    const uint2* hh = reinterpret_cast<const uint2*>(g_hh);

    unsigned long long accA = 0ull, accB = 0ull;   // packed (c0,c1), (c2,c3)
    float ssum = 0.f;

    #define ACCUM(V, WT) { \
        float2 f0 = __half22float2(*reinterpret_cast<__half2*>(&(V).x)); \
        float2 f1 = __half22float2(*reinterpret_cast<__half2*>(&(V).y)); \
        unsigned long long ww = pack_f2(make_float2((WT), (WT))); \
        FMA_F32X2(accA, ww, pack_f2(f0), accA); \
        FMA_F32X2(accB, ww, pack_f2(f1), accB); }

    int e = 0;
    for (; e + 4 <= cnt; e += 4) {
        int4 m01 = *reinterpret_cast<const int4*>(row + e);
        int4 m23 = *reinterpret_cast<const int4*>(row + e + 2);
        float w0 = __int_as_float(m01.y), w1 = __int_as_float(m01.w);
        float w2 = __int_as_float(m23.y), w3 = __int_as_float(m23.w);
        uint2 v0 = hh[(unsigned int)m01.x * 32u + lane];
        uint2 v1 = hh[(unsigned int)m01.z * 32u + lane];
        uint2 v2 = hh[(unsigned int)m23.x * 32u + lane];
        uint2 v3 = hh[(unsigned int)m23.z * 32u + lane];
        ACCUM(v0, w0) ACCUM(v1, w1) ACCUM(v2, w2) ACCUM(v3, w3)
        ssum += (w0 + w1) + (w2 + w3);
    }
    for (; e < cnt; e++) {
        int2 ee = row[e];
        float w0 = __int_as_float(ee.y);
        uint2 v0 = hh[(unsigned int)ee.x * 32u + lane];
        ACCUM(v0, w0)
        ssum += w0;
    }
    #undef ACCUM

    float2 rA = *reinterpret_cast<float2*>(&accA);
    float2 rB = *reinterpret_cast<float2*>(&accB);
    float inv = (ssum > 0.f) ? (1.f / ssum) : 0.f;
    reinterpret_cast<float4*>(out)[(unsigned int)w * 32u + lane] =
        make_float4(rA.x * inv, rA.y * inv, rB.x * inv, rB.y * inv);
}

// ---------------------------------------------------------------------------
extern "C" void kernel_launch(void* const* d_in, const int* in_sizes, int n_in,
                              void* d_out, int out_size)
{
    const float* X    = (const float*)d_in[0];   // node_states (50000,128)
    const int4*  E4   = (const int4*) d_in[1];   // edges as 2-edge packs
    const float* W    = (const float*)d_in[2];   // kernel (128,128)
    const float* attn = (const float*)d_in[3];   // kernel_attention (256,1)
    float* out = (float*)d_out;

    gemm_score_mma<<<GEMM_BLOCKS, 256>>>(X, W, attn);
    scatter_kernel<<<SCAT_BLOCKS, 256>>>(E4);
    agg_kernel<<<(N_NODES * 32 + 255) / 256, 256>>>(out);
}